// round 5
// baseline (speedup 1.0000x reference)
#include <cuda_runtime.h>
#include <math.h>

#define CC 10

static const int BLOCK = 256;
static const int GRID  = 1184;   // 8 * 148 SMs

// Per-block partials: [block][stat], 0..9 = sum p, 10..19 = sum p^2, 20..29 = sum log p
__device__ double g_partials[GRID][32];
__device__ unsigned int g_ticket = 0;   // reset by last block each call -> deterministic

// ---------------------------------------------------------------------------
// Fused branchless digamma + trigamma: unconditional shift x -> x+6
// (6 independent MUFU reciprocals shared between psi and psi'), then
// asymptotic series at y >= 6. abs err ~3e-9, fixed latency, full ILP.
// ---------------------------------------------------------------------------
__device__ __forceinline__ void psi01(float x, float& dg, float& tg) {
    float s0 = 0.f, s1 = 0.f;
#pragma unroll
    for (int k = 0; k < 6; k++) {
        float r = __fdividef(1.f, x + (float)k);
        s0 += r;
        s1  = fmaf(r, r, s1);
    }
    float y  = x + 6.f;
    float r  = __fdividef(1.f, y);
    float r2 = r * r;
    dg = __logf(y) - 0.5f * r
       - r2 * (0.0833333333f - r2 * (0.0083333333f - r2 * 0.0039682540f))
       - s0;
    tg = r + 0.5f * r2
       + r * r2 * (0.1666666667f - r2 * (0.0333333333f - r2 * 0.0238095238f))
       + s1;
}

// Paired butterfly allreduce over each 16-lane half (offsets 8,4,2,1).
__device__ __forceinline__ void allred2_16(float& v1, float& v2) {
#pragma unroll
    for (int o = 8; o > 0; o >>= 1) {
        v1 += __shfl_xor_sync(0xffffffffu, v1, o);
        v2 += __shfl_xor_sync(0xffffffffu, v2, o);
    }
}
__device__ __forceinline__ float allred1_16(float v) {
#pragma unroll
    for (int o = 8; o > 0; o >>= 1) v += __shfl_xor_sync(0xffffffffu, v, o);
    return v;
}

// ---------------------------------------------------------------------------
// Single fused kernel: stats pass + (last block) reduction + Newton solve.
// ---------------------------------------------------------------------------
__global__ __launch_bounds__(256) void ed_fused(const float* __restrict__ x,
                                                float* __restrict__ out, int n) {
    // ---------------- Phase 1: per-row softmax stats (unchanged math) -------
    float ap [CC];
    float ap2[CC];
    float alp[CC];
#pragma unroll
    for (int i = 0; i < CC; i++) { ap[i] = 0.f; ap2[i] = 0.f; alp[i] = 0.f; }

    const int stride = blockDim.x * gridDim.x;
    for (int r = blockIdx.x * blockDim.x + threadIdx.x; r < n; r += stride) {
        const float2* row = reinterpret_cast<const float2*>(x) + r * 5;
        float v[CC];
#pragma unroll
        for (int j = 0; j < 5; j++) {
            float2 t = __ldg(row + j);
            v[2 * j] = t.x; v[2 * j + 1] = t.y;
        }
        float mx = v[0];
#pragma unroll
        for (int i = 1; i < CC; i++) mx = fmaxf(mx, v[i]);
        float e[CC];
        float s = 0.f;
#pragma unroll
        for (int i = 0; i < CC; i++) { e[i] = __expf(v[i] - mx); s += e[i]; }
        float inv = 1.0f / s;
        float ls  = __logf(s);
#pragma unroll
        for (int i = 0; i < CC; i++) {
            float p  = e[i] * inv;
            ap [i] += p;
            ap2[i]  = fmaf(p, p, ap2[i]);
            alp[i] += (v[i] - mx) - ls;
        }
    }

#pragma unroll
    for (int i = 0; i < CC; i++) {
#pragma unroll
        for (int o = 16; o > 0; o >>= 1) {
            ap [i] += __shfl_down_sync(0xffffffffu, ap [i], o);
            ap2[i] += __shfl_down_sync(0xffffffffu, ap2[i], o);
            alp[i] += __shfl_down_sync(0xffffffffu, alp[i], o);
        }
    }

    __shared__ float sh[30][8];
    const int lane = threadIdx.x & 31, w = threadIdx.x >> 5;
    if (lane == 0) {
#pragma unroll
        for (int i = 0; i < CC; i++) {
            sh[i     ][w] = ap [i];
            sh[10 + i][w] = ap2[i];
            sh[20 + i][w] = alp[i];
        }
    }
    __syncthreads();
    if (threadIdx.x < 30) {
        double s2 = 0.0;
#pragma unroll
        for (int w2 = 0; w2 < 8; w2++) s2 += (double)sh[threadIdx.x][w2];
        g_partials[blockIdx.x][threadIdx.x] = s2;
    }

    // ---------------- Phase 2: last block does the tail ---------------------
    __shared__ bool amLast;
    __threadfence();
    if (threadIdx.x == 0) {
        unsigned int t = atomicAdd(&g_ticket, 1u);
        amLast = (t == (unsigned int)(gridDim.x - 1));
    }
    __syncthreads();
    if (!amLast) return;

    if (threadIdx.x == 0) g_ticket = 0;   // reset for next graph replay
    __threadfence();

    // Reduce per-block partials: stat = tid>>3, 8 threads/stat, 148 loads each
    __shared__ double st[32];
    {
        const int tid  = threadIdx.x;
        const int stat = tid >> 3, j = tid & 7;
        double s = 0.0;
        if (stat < 30) {
#pragma unroll 4
            for (int b = j; b < GRID; b += 8) s += g_partials[b][stat];
        }
        s += __shfl_down_sync(0xffffffffu, s, 4, 8);
        s += __shfl_down_sync(0xffffffffu, s, 2, 8);
        s += __shfl_down_sync(0xffffffffu, s, 1, 8);
        if (stat < 30 && j == 0) st[stat] = s;
    }
    __syncthreads();

    // Newton solve on warp 0, components on lanes 0..9, FIXED 20 iterations.
    if (threadIdx.x < 32) {
        const int   l   = threadIdx.x;
        const bool  act = (l < CC);
        const double dn = (double)n;

        float m1  = act ? (float)(st[l]      / dn) : 0.f;
        float m2  = act ? (float)(st[10 + l] / dn) : 0.f;
        float lpa = act ? (float)(st[20 + l] / dn) : 0.f;

        // method-of-moments init
        float ratio = act ? (m1 - m2) / (m2 - m1 * m1) : 0.f;
        float rmean = allred1_16(ratio) * 0.1f;
        float a     = act ? m1 * rmean : 0.f;
        float asum  = allred1_16(a);
        if (!act) { a = 1.0f; asum = 20.0f; }  // benign psi args on idle lanes

        // Newton, rank-1 Hessian inverse; n cancels. One allreduce per iter:
        // sum(delta) = num - b*qs recovers the next asum for free.
#pragma unroll 1
        for (int k = 0; k < 20; k++) {
            float dga, tga, dgs, tgs;
            psi01(a,    dga, tga);
            psi01(asum, dgs, tgs);
            float g    = dgs - dga + lpa;
            float qinv = __fdividef(-1.f, tga);
            float num  = act ? g * qinv : 0.f;
            float qs   = act ? qinv     : 0.f;
            allred2_16(num, qs);
            float zinv = __fdividef(1.f, tgs);
            float b    = num / (zinv + qs);
            float dlt  = (g - b) * qinv;
            a    = act ? a - dlt : 1.0f;
            asum = act ? asum - (num - b * qs) : 20.0f;
        }
        if (act) out[l] = a;
    }
}

// ---------------------------------------------------------------------------
extern "C" void kernel_launch(void* const* d_in, const int* in_sizes, int n_in,
                              void* d_out, int out_size) {
    const float* x = (const float*)d_in[0];
    const int n = in_sizes[0] / CC;   // 2,000,000 rows
    ed_fused<<<GRID, BLOCK>>>(x, (float*)d_out, n);
}